// round 1
// baseline (speedup 1.0000x reference)
#include <cuda_runtime.h>

#define EPS 1e-10f
#define NSTATE 68

// Derived-constant block: [0..74] raw params, [75..80] precomputed composites.
__device__ float g_const[88];

__global__ void setup_consts_kernel(const float* __restrict__ params) {
    if (threadIdx.x == 0 && blockIdx.x == 0) {
        #pragma unroll 1
        for (int i = 0; i < 75; i++) g_const[i] = params[i];
        // RAF vemurafenib hill: kBRAF_eff = ka1 * IC50^n / (IC50^n + Vem^n + EPS)
        float hill = params[62];
        float ic50n = powf(params[61], hill);
        float vemn  = powf(params[57], hill);
        g_const[75] = params[0] * ic50n / (ic50n + vemn + EPS);
        // KSR trametinib hill: tram_ksr = K^n / (K^n + T^n + EPS)
        float nt  = params[56];
        float ktn = powf(params[55], nt);
        float tn  = powf(params[53], nt);
        g_const[76] = ktn / (ktn + tn + EPS);
        // feedback Michaelis ratios
        g_const[77] = params[27] / (params[22] + EPS);  // km_Dusp / (kDusps+EPS)
        g_const[78] = params[28] / (params[23] + EPS);  // km_Sprty / (kSproutyForm+EPS)
        // vemurafenib-scaled rates
        g_const[79] = params[58] * params[57];           // kDimerForm * Vem
        g_const[80] = params[60] * params[57];           // kParadoxCRAF * Vem
    }
}

__global__ __launch_bounds__(256)
void mapk_rhs_kernel(const float* __restrict__ y, float* __restrict__ out, int n) {
    int row = blockIdx.x * blockDim.x + threadIdx.x;
    if (row >= n) return;

    // ---- load 68 states as 17 float4 (272B row, 16B aligned) ----
    const float4* yv = reinterpret_cast<const float4*>(y + (size_t)row * NSTATE);
    float ys[NSTATE];
    #pragma unroll
    for (int i = 0; i < 17; i++) {
        float4 v = __ldg(&yv[i]);
        ys[4*i+0] = fmaxf(v.x, 0.0f);
        ys[4*i+1] = fmaxf(v.y, 0.0f);
        ys[4*i+2] = fmaxf(v.z, 0.0f);
        ys[4*i+3] = fmaxf(v.w, 0.0f);
    }

    // ---- uniform params (broadcast loads) ----
    const float ka1            = g_const[0];
    const float kr1            = g_const[1];
    const float kc1            = g_const[2];
    const float kpCraf         = g_const[3];
    const float kpMek          = g_const[4];
    const float kpErk          = g_const[5];
    const float kDegradEgfr    = g_const[6];
    const float kErkInbEgfr    = g_const[7];
    const float kShcDephos     = g_const[8];
    const float kptpDeg        = g_const[9];
    const float kGrb2CombShc   = g_const[10];
    const float kSprtyInbGrb2  = g_const[11];
    const float kSosCombGrb2   = g_const[12];
    const float kErkPhosSos    = g_const[13];
    const float kErkPhosPcraf  = g_const[14];
    const float kPcrafDegrad   = g_const[15];
    const float kErkPhosMek    = g_const[16];
    const float kMekDegrad     = g_const[17];
    const float kDuspInbErk    = g_const[18];
    const float kErkDeg        = g_const[19];
    const float kinbBraf       = g_const[20];
    const float kDuspStop      = g_const[21];
    const float kSprtyComeDown = g_const[24];
    const float kdegrad        = g_const[25];
    const float km_Dusp        = g_const[27];
    const float km_Sprty       = g_const[28];
    const float kErkDephos     = g_const[29];
    const float kDuspDeg       = g_const[30];
    const float kHer2_act      = g_const[31];
    const float kHer3_act      = g_const[32];
    const float kbEGFR         = g_const[33];
    const float kbHer2         = g_const[34];
    const float kbHer3         = g_const[35];
    const float kbIGFR         = g_const[36];
    const float kunb           = g_const[37];
    const float kPI3Krec       = g_const[38];
    const float kMTORfb        = g_const[39];
    const float kPIP2          = g_const[40];
    const float kPTEN          = g_const[41];
    const float kAkt           = g_const[42];
    const float kdegAKT        = g_const[43];
    const float kb1            = g_const[44];
    const float k43b1          = g_const[45];
    const float k4ebp1         = g_const[46];
    const float k4ebp1de       = g_const[47];
    const float kKSRphos       = g_const[48];
    const float kKSRdephos     = g_const[49];
    const float kMekByBraf     = g_const[50];
    const float kMekByCraf     = g_const[51];
    const float kMekByKSR      = g_const[52];
    const float kDimerDissoc   = g_const[59];
    const float kPDGFR_act     = g_const[63];
    const float kbPDGFR        = g_const[64];
    const float kS6Kphos       = g_const[65];
    const float kS6Kdephos     = g_const[66];
    const float kRAS_PI3K      = g_const[67];
    const float kERK_IRS       = g_const[68];
    const float kERK_PTEN      = g_const[69];
    const float kAKT_CRAF      = g_const[70];
    const float kS6K_IRS       = g_const[71];
    const float kERK_GAB1      = g_const[72];
    const float kAKT_TSC2      = g_const[73];
    const float kERK_RSK       = g_const[74];
    const float kBRAF_eff      = g_const[75];
    const float tram_ksr       = g_const[76];
    const float kmDuspRatio    = g_const[77];
    const float kmSprtyRatio   = g_const[78];
    const float kDimVem        = g_const[79];  // kDimerForm * Vem
    const float kParaVem       = g_const[80];  // kParadoxCRAF * Vem

    float d[NSTATE];

    // --- EGFR / Her2 / Her3 receptor modules ---
    d[0] = -ka1*ys[0] + kr1*ys[1];
    d[1] =  ka1*ys[0] - kr1*ys[1] - kc1*ys[1];
    d[2] =  kc1*ys[1] - kDegradEgfr*ys[2] - kErkInbEgfr*ys[28]*ys[2];
    d[3] = -kHer2_act*ys[3] + kr1*ys[4];
    d[4] =  kHer2_act*ys[3] - kr1*ys[4] - kc1*ys[4];
    d[5] =  kc1*ys[4] - kDegradEgfr*ys[5] - kErkInbEgfr*ys[28]*ys[5];
    d[6] = -kHer3_act*ys[6] + kr1*ys[7];
    d[7] =  kHer3_act*ys[6] - kr1*ys[7] - kc1*ys[7];
    d[8] =  kc1*ys[7] - kDegradEgfr*ys[8] - kErkInbEgfr*ys[28]*ys[8];

    // --- Shc / Grb2 / Sos / Ras ---
    float a29 = ka1*ys[2]*ys[9];
    d[9]  = -a29;
    d[10] =  a29 - kShcDephos*ys[11]*ys[10];
    d[11] = -kptpDeg*ys[10]*ys[11];
    d[12] =  kGrb2CombShc*ys[10]*ys[2] - kSprtyInbGrb2*ys[26]*ys[12];
    d[13] =  kSosCombGrb2*ys[12]*ys[10] - kErkPhosSos*ys[24]*ys[13];
    float s14 = ka1*ys[13]*ys[14];
    d[14] = -s14;
    d[15] =  s14;
    float s16 = ka1*ys[13]*ys[16];
    d[16] = -s16;
    d[17] =  s16;
    float s18 = ka1*ys[13]*ys[18];
    float s19 = ka1*ys[19]*ys[20];
    d[18] = -s18;
    d[19] =  s18 - s19;
    d[20] = -s19;

    // --- RAF with vemurafenib paradox ---
    float paradox   = kParaVem * ys[61];
    float akt_craf  = kAKT_CRAF*ys[52]*ys[21];
    float dimF      = kDimVem*ys[24]*ys[21];
    float dimD      = kDimerDissoc*ys[61];
    float craf_fwd  = kpCraf*ys[19]*ys[21];
    float craf_rev  = kErkPhosPcraf*ys[28]*ys[22];
    float craf_deg  = kPcrafDegrad*ys[22]*ys[35];
    float braf_act  = kBRAF_eff*ys[23]*ys[19];
    d[21] = -craf_fwd + craf_rev + craf_deg - dimF + dimD - akt_craf;
    d[22] =  craf_fwd - craf_rev - craf_deg + paradox;
    d[23] = -braf_act - dimF + dimD;
    d[24] =  braf_act - kinbBraf*ys[24] - dimF + dimD;
    d[61] =  dimF - dimD - kPcrafDegrad*ys[61]*ys[35];

    // --- MEK / ERK ---
    float raf_to_mek = kpMek*ys[22] + kMekByBraf*ys[24] + kMekByCraf*ys[22];
    float ksr_to_mek = kMekByKSR*ys[60];
    float mek_fwd    = (raf_to_mek + ksr_to_mek)*ys[25];
    float mek_rev    = kErkPhosMek*ys[28]*ys[26];
    float mek_deg    = kMekDegrad*ys[26]*ys[34];
    d[25] = -mek_fwd + mek_rev + mek_deg;
    d[26] =  mek_fwd - mek_rev - mek_deg;
    float erk_fwd = kpErk*ys[26]*ys[27];
    float erk_bk  = kDuspInbErk*ys[30]*ys[28] + kErkDeg*ys[28]*ys[33] + kErkDephos*ys[30]*ys[28];
    d[27] = -erk_fwd + erk_bk;
    d[28] =  erk_fwd - erk_bk;

    // --- DUSP / Sprouty feedback ---
    float denom_dusp = 1.0f + kmDuspRatio*ys[28];
    d[29] = km_Dusp*ys[28]/(denom_dusp + EPS) - kDuspStop*ys[29]*ys[36] - kDuspDeg*ys[29]*ys[28];
    d[30] = -kDuspStop*ys[29]*ys[30];
    float denom_spry = 1.0f + kmSprtyRatio*ys[28];
    float spry_dn = kSprtyComeDown*ys[31]*ys[32];
    d[31] = km_Sprty*ys[28]/(denom_spry + EPS) - spry_dn;
    d[32] = -spry_dn;
    d[33] = -kErkDeg*ys[28]*ys[33];
    d[34] = -mek_deg;
    d[35] = -craf_deg;
    d[36] = -kDuspStop*ys[29]*ys[36];

    // --- IGFR / IRS ---
    d[37] = -ka1*ys[37] + kr1*ys[38];
    d[38] =  ka1*ys[37] - kr1*ys[38] - kc1*ys[38];
    d[39] =  kc1*ys[38] - kErkInbEgfr*ys[28]*ys[39];
    float erk_irs = kERK_IRS*ys[28]*ys[41];
    float s6k_irs = kS6K_IRS*ys[66]*ys[41];
    float irs_fwd = ka1*ys[2]*ys[40];
    d[40] = -irs_fwd + erk_irs + s6k_irs;
    d[41] =  irs_fwd - erk_irs - s6k_irs;

    // --- p85 binding ---
    float gab1 = 1.0f / (1.0f + kERK_GAB1*ys[28]);
    float bE = kbEGFR*ys[2]*ys[42]*gab1;
    float bH2 = kbHer2*ys[5]*ys[42]*gab1;
    float bH3 = kbHer3*ys[8]*ys[42]*gab1;
    float bI = kbIGFR*ys[39]*ys[42];
    float bP = kbPDGFR*ys[64]*ys[42];
    float sum_p85c = ys[43] + ys[44] + ys[45] + ys[46] + ys[67];
    d[42] = -bE - bH2 - bH3 - bI - bP + kunb*sum_p85c;
    d[43] = bE  - kunb*ys[43];
    d[44] = bH2 - kunb*ys[44];
    d[45] = bH3 - kunb*ys[45];
    d[46] = bI  - kunb*ys[46];
    d[67] = bP  - kunb*ys[67];

    // --- PI3K / AKT / mTOR axis ---
    float pi3k_act = kPI3Krec*sum_p85c*ys[47] + kRAS_PI3K*ys[15]*ys[47];
    float mtor_fb  = kMTORfb*ys[56]*ys[48];
    d[47] = -pi3k_act + mtor_fb;
    d[48] =  pi3k_act - mtor_fb;
    float pip_fwd = kPIP2*ys[48]*ys[49];
    float pip_rev = kPTEN*ys[51]*ys[50];
    d[49] = -pip_fwd + pip_rev;
    d[50] =  pip_fwd - pip_rev;
    d[51] = kERK_PTEN*ys[28] - kdegrad*ys[51];
    float akt_fwd = kAkt*ys[50]*ys[53];
    float akt_rev = kdegAKT*ys[52];
    d[52] =  akt_fwd - akt_rev;
    d[53] = -akt_fwd + akt_rev;
    float tsc = kAKT_TSC2*ys[52]*ys[54];
    d[54] = -tsc;
    d[55] =  tsc - kdegrad*ys[55];
    float mtor_fwd = kb1*ys[52]*ys[57];
    float mtor_rev = k43b1*ys[56];
    d[56] =  mtor_fwd - mtor_rev;
    d[57] = -mtor_fwd + mtor_rev;
    float ebp_fwd = k4ebp1*ys[56]*ys[58];
    float ebp_rev = k4ebp1de*ys[59];
    d[58] = -ebp_fwd + ebp_rev;
    d[59] =  ebp_fwd - ebp_rev;

    // --- KSR with trametinib hill factor ---
    float ksr_fwd = kKSRphos*ys[19]*ys[62]*tram_ksr;
    float ksr_rev = kKSRdephos*ys[60];
    d[60] =  ksr_fwd - ksr_rev;
    d[62] = -ksr_fwd + ksr_rev;

    // --- PDGFR ---
    d[63] = -kPDGFR_act*ys[63];
    d[64] =  kPDGFR_act*ys[63] - kDegradEgfr*ys[64];

    // --- S6K ---
    float s6_fwd = kS6Kphos*ys[56]*ys[65];
    float rsk    = kERK_RSK*ys[28]*ys[65];
    float s6_rev = kS6Kdephos*ys[66];
    d[65] = -s6_fwd + s6_rev - rsk;
    d[66] =  s6_fwd - s6_rev + rsk;

    // ---- store 68 derivatives as 17 float4 ----
    float4* ov = reinterpret_cast<float4*>(out + (size_t)row * NSTATE);
    #pragma unroll
    for (int i = 0; i < 17; i++) {
        float4 v;
        v.x = d[4*i+0]; v.y = d[4*i+1]; v.z = d[4*i+2]; v.w = d[4*i+3];
        ov[i] = v;
    }
}

extern "C" void kernel_launch(void* const* d_in, const int* in_sizes, int n_in,
                              void* d_out, int out_size) {
    // inputs per metadata order: t (1), y (B*68), params (75)
    const float* y      = (const float*)d_in[1];
    const float* params = (const float*)d_in[2];
    float* out = (float*)d_out;

    int n = in_sizes[1] / NSTATE;  // number of rows (B)

    setup_consts_kernel<<<1, 32>>>(params);

    int threads = 256;
    int blocks = (n + threads - 1) / threads;
    mapk_rhs_kernel<<<blocks, threads>>>(y, out, n);
}